// round 4
// baseline (speedup 1.0000x reference)
#include <cuda_runtime.h>
#include <cuda_bf16.h>
#include <cstdint>

typedef unsigned long long ull;

// ---------------- f32x2 packed helpers (Blackwell) ----------------
__device__ __forceinline__ ull ffma2(ull a, ull b, ull c) {
    ull d;
    asm("fma.rn.f32x2 %0, %1, %2, %3;" : "=l"(d) : "l"(a), "l"(b), "l"(c));
    return d;
}
__device__ __forceinline__ ull pack2(float lo, float hi) {
    ull r;
    asm("mov.b64 %0, {%1, %2};" : "=l"(r) : "f"(lo), "f"(hi));
    return r;
}
__device__ __forceinline__ void unpack2(ull v, float& lo, float& hi) {
    asm("mov.b64 {%0, %1}, %2;" : "=f"(lo), "=f"(hi) : "l"(v));
}
__device__ __forceinline__ ull relu2(ull v) {
    float lo, hi;
    unpack2(v, lo, hi);
    return pack2(fmaxf(lo, 0.0f), fmaxf(hi, 0.0f));
}

static constexpr int C = 16;
static constexpr int TPB = 256;

// 4 rows per thread (two f32x2 row-pairs). Register-pressure-shaped:
//  - GEMM1 consumes input chunks as h accumulators come alive (peak ~120)
//  - GEMM2 streams 4-output chunks straight to STG.128 (no o[] array)
__global__ __launch_bounds__(TPB, 2)
void dmasif_fused_kernel(const float* __restrict__ feat,
                         float* __restrict__ out,
                         const float* __restrict__ Wt,
                         const float* __restrict__ bt,
                         const float* __restrict__ Wa,
                         const float* __restrict__ ba,
                         const float* __restrict__ Wb,
                         const float* __restrict__ bb,
                         long long n)
{
    __shared__ ull sWc[C * C];   // folded Wc = Wa @ Wt, [o*16+i], (w,w) packed
    __shared__ ull sWb[C * C];   // Wb, [q*16+o], (w,w) packed
    __shared__ ull sbc[C];
    __shared__ ull sbb[C];

    const int t = threadIdx.x;
    {
        const int o = t >> 4;
        const int i = t & 15;
        float acc = 0.0f;
#pragma unroll
        for (int m = 0; m < C; m++)
            acc += Wa[o * C + m] * Wt[m * C + i];
        sWc[t] = pack2(acc, acc);
        const float wb = Wb[t];
        sWb[t] = pack2(wb, wb);
        if (t < C) {
            float b = ba[t];
#pragma unroll
            for (int m = 0; m < C; m++)
                b += Wa[t * C + m] * bt[m];
            sbc[t] = pack2(b, b);
            const float b2 = bb[t];
            sbb[t] = pack2(b2, b2);
        }
    }
    __syncthreads();

    const long long base = ((long long)blockIdx.x * TPB + t) * 4;
    if (base >= n) return;
    const bool full = (base + 4 <= n);

    // ---- load 4 rows of features, pack into two row-pairs ----
    ull p0[C], p1[C];
    if (full) {
        const float4* f4 = reinterpret_cast<const float4*>(feat + base * C);
        float4 ra[4], rb[4], rc[4], rd[4];
#pragma unroll
        for (int j = 0; j < 4; j++) {
            ra[j] = f4[0 * 4 + j];
            rb[j] = f4[1 * 4 + j];
            rc[j] = f4[2 * 4 + j];
            rd[j] = f4[3 * 4 + j];
        }
#pragma unroll
        for (int j = 0; j < 4; j++) {
            p0[4 * j + 0] = pack2(ra[j].x, rb[j].x);
            p0[4 * j + 1] = pack2(ra[j].y, rb[j].y);
            p0[4 * j + 2] = pack2(ra[j].z, rb[j].z);
            p0[4 * j + 3] = pack2(ra[j].w, rb[j].w);
            p1[4 * j + 0] = pack2(rc[j].x, rd[j].x);
            p1[4 * j + 1] = pack2(rc[j].y, rd[j].y);
            p1[4 * j + 2] = pack2(rc[j].z, rd[j].z);
            p1[4 * j + 3] = pack2(rc[j].w, rd[j].w);
        }
    } else {
        float rA[C], rB[C], rC[C], rD[C];
#pragma unroll
        for (int i = 0; i < C; i++) { rA[i] = 0.f; rB[i] = 0.f; rC[i] = 0.f; rD[i] = 0.f; }
        if (base + 0 < n) { for (int i = 0; i < C; i++) rA[i] = feat[(base + 0) * C + i]; }
        if (base + 1 < n) { for (int i = 0; i < C; i++) rB[i] = feat[(base + 1) * C + i]; }
        if (base + 2 < n) { for (int i = 0; i < C; i++) rC[i] = feat[(base + 2) * C + i]; }
        if (base + 3 < n) { for (int i = 0; i < C; i++) rD[i] = feat[(base + 3) * C + i]; }
#pragma unroll
        for (int i = 0; i < C; i++) {
            p0[i] = pack2(rA[i], rB[i]);
            p1[i] = pack2(rC[i], rD[i]);
        }
    }

    // ---- GEMM1 + ReLU: h = relu(f @ Wc^T + bc), i-chunked so p dies as h fills ----
    ull h0[C], h1[C];
#pragma unroll
    for (int o = 0; o < C; o++) {
        ull a0 = sbc[o];
        ull a1 = a0;
#pragma unroll
        for (int ii = 0; ii < 4; ii++) {
            const ull w = sWc[o * C + ii];
            a0 = ffma2(p0[ii], w, a0);
            a1 = ffma2(p1[ii], w, a1);
        }
        h0[o] = a0;
        h1[o] = a1;
    }
#pragma unroll
    for (int ic = 1; ic < 4; ic++) {
#pragma unroll
        for (int o = 0; o < C; o++) {
            ull a0 = h0[o];
            ull a1 = h1[o];
#pragma unroll
            for (int ii = 0; ii < 4; ii++) {
                const int i = 4 * ic + ii;
                const ull w = sWc[o * C + i];
                a0 = ffma2(p0[i], w, a0);
                a1 = ffma2(p1[i], w, a1);
            }
            h0[o] = a0;
            h1[o] = a1;
        }
    }
#pragma unroll
    for (int o = 0; o < C; o++) {
        h0[o] = relu2(h0[o]);
        h1[o] = relu2(h1[o]);
    }

    // ---- GEMM2: out = h @ Wb^T + bb, streamed 4-output chunks -> STG.128 ----
    float4* g4 = reinterpret_cast<float4*>(out + base * C);
#pragma unroll
    for (int qc = 0; qc < 4; qc++) {
        float vA[4], vB[4], vC[4], vD[4];
#pragma unroll
        for (int qq = 0; qq < 4; qq++) {
            const int q = 4 * qc + qq;
            ull a0 = sbb[q];
            ull a1 = a0;
#pragma unroll
            for (int o = 0; o < C; o++) {
                const ull w = sWb[q * C + o];
                a0 = ffma2(h0[o], w, a0);
                a1 = ffma2(h1[o], w, a1);
            }
            unpack2(a0, vA[qq], vB[qq]);
            unpack2(a1, vC[qq], vD[qq]);
        }
        if (full) {
            g4[0 * 4 + qc] = make_float4(vA[0], vA[1], vA[2], vA[3]);
            g4[1 * 4 + qc] = make_float4(vB[0], vB[1], vB[2], vB[3]);
            g4[2 * 4 + qc] = make_float4(vC[0], vC[1], vC[2], vC[3]);
            g4[3 * 4 + qc] = make_float4(vD[0], vD[1], vD[2], vD[3]);
        } else {
#pragma unroll
            for (int qq = 0; qq < 4; qq++) {
                const int q = 4 * qc + qq;
                if (base + 0 < n) out[(base + 0) * C + q] = vA[qq];
                if (base + 1 < n) out[(base + 1) * C + q] = vB[qq];
                if (base + 2 < n) out[(base + 2) * C + q] = vC[qq];
                if (base + 3 < n) out[(base + 3) * C + q] = vD[qq];
            }
        }
    }
}

extern "C" void kernel_launch(void* const* d_in, const int* in_sizes, int n_in,
                              void* d_out, int out_size)
{
    // metadata order: features, points, nuv, Wt, bt, Wa, ba, Wb, bb, ranges
    const float* feat = (const float*)d_in[0];
    const float* Wt   = (const float*)d_in[3];
    const float* bt   = (const float*)d_in[4];
    const float* Wa   = (const float*)d_in[5];
    const float* ba   = (const float*)d_in[6];
    const float* Wb   = (const float*)d_in[7];
    const float* bb   = (const float*)d_in[8];
    float* out = (float*)d_out;

    const long long n = (long long)in_sizes[0] / C;
    const long long quads = (n + 3) / 4;
    const int blocks = (int)((quads + TPB - 1) / TPB);

    dmasif_fused_kernel<<<blocks, TPB>>>(feat, out, Wt, bt, Wa, ba, Wb, bb, n);
}